// round 12
// baseline (speedup 1.0000x reference)
#include <cuda_runtime.h>
#include <cuda_bf16.h>
#include <math.h>
#include <stdint.h>

// GraphRNN: 2-layer LayerNorm-GRU scan. B=16, T=24, N=207, D=512, G=1536.
// R12: bf16-k16 3x-split GEMMs with BK=32 (two k16 MMA groups per pipeline
//      stage -> half the sync/loop overhead). 128x64 tiles @ 3 CTAs/SM.
//      Stream structure and packing layouts unchanged from R11.
namespace {
constexpr int B_ = 16, T_ = 24, N_ = 207, D_ = 512, G_ = 1536;
constexpr int MR  = B_ * N_;        // 3312 rows per timestep
constexpr int MRP = 3328;           // padded: 26*128
constexpr int MB_ = B_ * T_ * N_;   // 79488

constexpr int NCF = D_ / 16;        // 32 fine chunks (packing granularity)
constexpr int NCC = D_ / 32;        // 16 coarse chunks (pipeline granularity)
constexpr int CT_ = G_ / 64;        // 24 col-tiles of 64
constexpr int RT_R = MRP / 128;     // 26 row-tiles per timestep

// fine-chunk packing (unchanged from R11):
constexpr int A_QF = 512, B_QF = 256;
// coarse stage: 2 fine chunks
constexpr int A_QC = 1024, B_QC = 512;
constexpr int STAGE_Q = A_QC + B_QC;   // 1536 quads = 24KB
constexpr int STAGES = 3;
constexpr int SMEM_BYTES = STAGES * STAGE_Q * 16;  // 73728

constexpr size_t WQ_PER_W = (size_t)CT_ * NCF * B_QF;   // 196608
constexpr size_t HQ  = (size_t)RT_R * NCF * A_QF;       // packed rows / t
constexpr size_t XQ  = (size_t)T_ * HQ;
}

// ---------------- scratch (device globals; zero-initialized) ----------------
__device__ float g_gi0[(size_t)T_ * MRP * G_];   // t-major
__device__ float g_gh0[(size_t)MRP * G_];
__device__ float g_gi1[(size_t)MRP * G_];
__device__ float g_gh1[(size_t)MRP * G_];
__device__ float g_h0s[(size_t)MRP * D_];
__device__ float g_h1s[(size_t)MRP * D_];
__device__ uint4 g_h0p[2 * HQ];                  // double-buffered (parity t&1)
__device__ uint4 g_h1p[HQ];
__device__ uint4 g_xp[XQ];                       // t-major packed x
__device__ uint4 g_Wp[4 * WQ_PER_W];

// ---------------- helpers ----------------
__device__ __forceinline__ uint32_t smem_u32(const void* p) {
    uint32_t a;
    asm("{ .reg .u64 t; cvta.to.shared.u64 t, %1; cvt.u32.u64 %0, t; }"
        : "=r"(a) : "l"(p));
    return a;
}
#define CP_ASYNC16(dst, src) \
    asm volatile("cp.async.cg.shared.global [%0], [%1], 16;" :: "r"(dst), "l"(src))
#define CP_COMMIT() asm volatile("cp.async.commit_group;" ::: "memory")
template <int N>
__device__ __forceinline__ void cp_wait() {
    asm volatile("cp.async.wait_group %0;" :: "n"(N) : "memory");
}

// bf16 hi/lo split of a float
__device__ __forceinline__ void split_bf16(float x, uint16_t& hi, uint16_t& lo) {
    __nv_bfloat16 h = __float2bfloat16_rn(x);
    float hf = __bfloat162float(h);
    __nv_bfloat16 l = __float2bfloat16_rn(x - hf);
    hi = *reinterpret_cast<uint16_t*>(&h);
    lo = *reinterpret_cast<uint16_t*>(&l);
}
__device__ __forceinline__ uint32_t pack2(uint16_t a, uint16_t b) {
    return (uint32_t)a | ((uint32_t)b << 16);
}

#define MMA_BF16(d, a, b0, b1)                                              \
    asm volatile("mma.sync.aligned.m16n8k16.row.col.f32.bf16.bf16.f32 "     \
        "{%0,%1,%2,%3}, {%4,%5,%6,%7}, {%8,%9}, {%0,%1,%2,%3};"             \
        : "+f"((d)[0]), "+f"((d)[1]), "+f"((d)[2]), "+f"((d)[3])            \
        : "r"((a)[0]), "r"((a)[1]), "r"((a)[2]), "r"((a)[3]),               \
          "r"(b0), "r"(b1))

// ---------------------------------------------------------------------------
// Packed-activation writer (fine-chunk layout, unchanged from R11).
// ---------------------------------------------------------------------------
__device__ __forceinline__ void write_packed_bf16(uint32_t* Ap, int m, int d0,
                                                  const float* y) {
    int rt = m >> 7, mrow = m & 127;
    int mg = mrow >> 4, rr = mrow & 15;
    int ch = d0 >> 4, kd = d0 & 15;
    int khalf = kd >> 3;
    int tgb = (kd & 7) >> 1;
    int s = (rr >> 3) + 2 * khalf;
    size_t base = ((size_t)rt * NCF + ch) * A_QF;
    uint16_t h0, l0, h1, l1;
#pragma unroll
    for (int j = 0; j < 2; j++) {
        split_bf16(y[2 * j],     h0, l0);
        split_bf16(y[2 * j + 1], h1, l1);
        int lane = (rr & 7) * 4 + tgb + j;
        size_t qhi = base + (size_t)mg * 32 + lane;
        Ap[qhi * 4 + s]         = pack2(h0, h1);
        Ap[(qhi + 256) * 4 + s] = pack2(l0, l1);
    }
}

// ---------------------------------------------------------------------------
// GEMM core (128x64 C tile), BK=32 stage: [A fc0 | A fc1 | B fc0 | B fc1].
// 256 thr, 8 warps (warpM 0..3 x warpN 0..1).
// ---------------------------------------------------------------------------
__device__ __forceinline__ void load_stage(uint32_t sS, const uint4* __restrict__ Aq,
                                           const uint4* __restrict__ Bq,
                                           int ch, int tid) {
    const uint4* a = Aq + (size_t)ch * A_QC;   // 2 fine chunks contiguous
    const uint4* b = Bq + (size_t)ch * B_QC;
#pragma unroll
    for (int i = 0; i < 4; i++) {
        int s = tid + i * 256;
        CP_ASYNC16(sS + (uint32_t)s * 16u, a + s);
    }
#pragma unroll
    for (int i = 0; i < 2; i++) {
        int s = tid + i * 256;
        CP_ASYNC16(sS + (uint32_t)(A_QC + s) * 16u, b + s);
    }
}

__device__ __forceinline__ void bf16_gemm_core(const uint4* __restrict__ Ap,
                                               const uint4* __restrict__ Wp,
                                               const float* __restrict__ bias,
                                               float* __restrict__ C) {
    extern __shared__ uint4 smq[];

    const int tid  = threadIdx.x;
    const int lane = tid & 31, warp = tid >> 5;
    const int warpM = warp & 3, warpN = warp >> 2;
    const int r  = lane >> 2;
    const int qk = lane & 3;

    const uint4* Aq = Ap + (size_t)blockIdx.y * (NCF * A_QF);
    const uint4* Bq = Wp + (size_t)blockIdx.x * (NCF * B_QF);

    float acc[2][4][4];
#pragma unroll
    for (int mt = 0; mt < 2; mt++)
#pragma unroll
        for (int nt = 0; nt < 4; nt++)
#pragma unroll
            for (int i = 0; i < 4; i++) acc[mt][nt][i] = 0.f;

    uint32_t sb = smem_u32(smq);
    load_stage(sb, Aq, Bq, 0, tid);
    CP_COMMIT();
    load_stage(sb + STAGE_Q * 16, Aq, Bq, 1, tid);
    CP_COMMIT();

    for (int ch = 0; ch < NCC; ch++) {
        if (ch < NCC - 1) cp_wait<1>(); else cp_wait<0>();
        __syncthreads();
        if (ch + 2 < NCC) {
            load_stage(sb + ((ch + 2) % STAGES) * (STAGE_Q * 16), Aq, Bq, ch + 2, tid);
            CP_COMMIT();
        }
        const uint4* St = smq + (size_t)(ch % STAGES) * STAGE_Q;

#pragma unroll
        for (int u = 0; u < 2; u++) {
            const uint4* As = St + u * A_QF;
            const uint4* Bs = St + A_QC + u * B_QF;

            uint4 ah[2], al[2];
#pragma unroll
            for (int mt = 0; mt < 2; mt++) {
                int mg = warpM * 2 + mt;
                ah[mt] = As[mg * 32 + lane];
                al[mt] = As[mg * 32 + lane + 256];
            }
            uint4 bf[4];
#pragma unroll
            for (int j = 0; j < 4; j++) {
                int g = warpN * 4 + j;
                bf[j] = Bs[g * 32 + lane];
            }
            // pass 1: al * bh
#pragma unroll
            for (int j = 0; j < 4; j++)
#pragma unroll
                for (int mt = 0; mt < 2; mt++)
                    MMA_BF16(acc[mt][j], ((const uint32_t*)&al[mt]),
                             bf[j].x, bf[j].y);
            // pass 2: ah * bl
#pragma unroll
            for (int j = 0; j < 4; j++)
#pragma unroll
                for (int mt = 0; mt < 2; mt++)
                    MMA_BF16(acc[mt][j], ((const uint32_t*)&ah[mt]),
                             bf[j].z, bf[j].w);
            // pass 3: ah * bh
#pragma unroll
            for (int j = 0; j < 4; j++)
#pragma unroll
                for (int mt = 0; mt < 2; mt++)
                    MMA_BF16(acc[mt][j], ((const uint32_t*)&ah[mt]),
                             bf[j].x, bf[j].y);
        }
    }

    const int brow = blockIdx.y * 128;
    const int bcol = blockIdx.x * 64;
    const int q2 = qk * 2;
#pragma unroll
    for (int mt = 0; mt < 2; mt++) {
        const int row0 = brow + warpM * 32 + mt * 16 + r;
#pragma unroll
        for (int nt = 0; nt < 4; nt++) {
            const int col = bcol + warpN * 32 + nt * 8 + q2;
            const float2 bv = *reinterpret_cast<const float2*>(bias + col);
            float2 v0 = make_float2(acc[mt][nt][0] + bv.x, acc[mt][nt][1] + bv.y);
            float2 v1 = make_float2(acc[mt][nt][2] + bv.x, acc[mt][nt][3] + bv.y);
            *reinterpret_cast<float2*>(C + (size_t)row0 * G_ + col) = v0;
            *reinterpret_cast<float2*>(C + (size_t)(row0 + 8) * G_ + col) = v1;
        }
    }
}

__global__ void __launch_bounds__(256, 3)
bf16_gemm1_kernel(const uint4* __restrict__ Ap, const uint4* __restrict__ Wp,
                  const float* __restrict__ bias, float* __restrict__ C) {
    bf16_gemm_core(Ap, Wp, bias, C);
}

__global__ void __launch_bounds__(256, 3)
bf16_gemm2_kernel(const uint4* A0, const uint4* P0, const float* b0, float* C0,
                  const uint4* A1, const uint4* P1, const float* b1, float* C1) {
    const uint4* A; const uint4* P; const float* bias; float* C;
    if (blockIdx.z == 0) { A = A0; P = P0; bias = b0; C = C0; }
    else                 { A = A1; P = P1; bias = b1; C = C1; }
    bf16_gemm_core(A, P, bias, C);
}

// ---------------------------------------------------------------------------
// Weight prepack (fine-chunk granularity, unchanged from R11).
// ---------------------------------------------------------------------------
__global__ void prepack_kernel(const float* __restrict__ Wi,
                               const float* __restrict__ Wh,
                               uint4* __restrict__ Wp) {
    __shared__ float tile[16][64];
    const int ct = blockIdx.x, ch = blockIdx.y, z = blockIdx.z;
    const float* src = (z < 2 ? Wi : Wh) + (size_t)(z & 1) * D_ * G_;
    const int tid = threadIdx.x;

#pragma unroll
    for (int i = 0; i < 4; i++) {
        int s = tid + i * 256;
        int kk = s >> 6, n = s & 63;
        tile[kk][n] = src[(size_t)(ch * 16 + kk) * G_ + ct * 64 + n];
    }
    __syncthreads();

    uint4* dst = Wp + ((size_t)z * CT_ + ct) * (NCF * B_QF) + (size_t)ch * B_QF;
    if (tid < 256) {
        int lane = tid & 31, g = tid >> 5;
        int nl = g * 8 + (lane >> 2);
        int tg = lane & 3;
        uint16_t h0a, l0a, h0b, l0b, h1a, l1a, h1b, l1b;
        split_bf16(tile[2 * tg][nl],     h0a, l0a);
        split_bf16(tile[2 * tg + 1][nl], h0b, l0b);
        split_bf16(tile[2 * tg + 8][nl], h1a, l1a);
        split_bf16(tile[2 * tg + 9][nl], h1b, l1b);
        uint4 q;
        q.x = pack2(h0a, h0b);
        q.y = pack2(h1a, h1b);
        q.z = pack2(l0a, l0b);
        q.w = pack2(l1a, l1b);
        dst[tid] = q;
    }
}

// ---------------------------------------------------------------------------
// x prepack: x row (b,t,n) -> t-major packed row t*MRP + b*N + n
// ---------------------------------------------------------------------------
__global__ void xpack_kernel(const float* __restrict__ x, uint4* __restrict__ xp) {
    int min_ = blockIdx.x;
    int n = min_ % N_;
    int t = (min_ / N_) % T_;
    int b = min_ / (N_ * T_);
    int m = t * MRP + b * N_ + n;
    int tid = threadIdx.x;
    float4 v = reinterpret_cast<const float4*>(x + (size_t)min_ * D_)[tid];
    float y[4] = { v.x, v.y, v.z, v.w };
    write_packed_bf16((uint32_t*)xp, m, tid * 4, y);
}

// ---------------------------------------------------------------------------
// Fused GRU cell + LayerNorm
// ---------------------------------------------------------------------------
__device__ __forceinline__ float sigf(float v) { return 1.f / (1.f + expf(-v)); }

__device__ __forceinline__ void cell_body(const float* __restrict__ gi,
                                          const float* __restrict__ ghrow,
                                          float* __restrict__ hrow,
                                          uint32_t* __restrict__ hpack, int m,
                                          const float* __restrict__ gamma,
                                          const float* __restrict__ beta,
                                          float* __restrict__ o2) {
    const float4* gi4 = reinterpret_cast<const float4*>(gi);
    const float4* gh4 = reinterpret_cast<const float4*>(ghrow);
    float4* h4 = reinterpret_cast<float4*>(hrow);
    int tid = threadIdx.x;

    float4 ir = gi4[tid], iz = gi4[128 + tid], inn = gi4[256 + tid];
    float4 hr = gh4[tid], hz = gh4[128 + tid], hn = gh4[256 + tid];
    float4 hv = h4[tid];

    float o[4];
    {
        float rr, z, nv;
        rr = sigf(ir.x + hr.x); z = sigf(iz.x + hz.x); nv = tanhf(inn.x + rr * hn.x);
        o[0] = nv + z * (hv.x - nv);
        rr = sigf(ir.y + hr.y); z = sigf(iz.y + hz.y); nv = tanhf(inn.y + rr * hn.y);
        o[1] = nv + z * (hv.y - nv);
        rr = sigf(ir.z + hr.z); z = sigf(iz.z + hz.z); nv = tanhf(inn.z + rr * hn.z);
        o[2] = nv + z * (hv.z - nv);
        rr = sigf(ir.w + hr.w); z = sigf(iz.w + hz.w); nv = tanhf(inn.w + rr * hn.w);
        o[3] = nv + z * (hv.w - nv);
    }
    float s = o[0] + o[1] + o[2] + o[3];
    float s2 = o[0]*o[0] + o[1]*o[1] + o[2]*o[2] + o[3]*o[3];
#pragma unroll
    for (int off = 16; off > 0; off >>= 1) {
        s  += __shfl_xor_sync(0xffffffffu, s,  off);
        s2 += __shfl_xor_sync(0xffffffffu, s2, off);
    }
    __shared__ float sh[4], sh2[4];
    int w = tid >> 5;
    if ((tid & 31) == 0) { sh[w] = s; sh2[w] = s2; }
    __syncthreads();
    s  = sh[0]  + sh[1]  + sh[2]  + sh[3];
    s2 = sh2[0] + sh2[1] + sh2[2] + sh2[3];
    float mu  = s * (1.f / D_);
    float var = s2 * (1.f / D_) - mu * mu;
    float inv = rsqrtf(var + 1e-5f);

    const float4 g4 = reinterpret_cast<const float4*>(gamma)[tid];
    const float4 b4 = reinterpret_cast<const float4*>(beta)[tid];
    float y[4];
    y[0] = (o[0] - mu) * inv * g4.x + b4.x;
    y[1] = (o[1] - mu) * inv * g4.y + b4.y;
    y[2] = (o[2] - mu) * inv * g4.z + b4.z;
    y[3] = (o[3] - mu) * inv * g4.w + b4.w;
    h4[tid] = make_float4(y[0], y[1], y[2], y[3]);
    write_packed_bf16(hpack, m, tid * 4, y);
    if (o2) reinterpret_cast<float4*>(o2)[tid] =
        make_float4(y[0], y[1], y[2], y[3]);
}

__global__ void __launch_bounds__(128)
gru_cell0(const float* __restrict__ gi0, int t,
          const float* __restrict__ gh, float* __restrict__ h,
          uint32_t* __restrict__ hpack,
          const float* __restrict__ gamma, const float* __restrict__ beta) {
    int m = blockIdx.x;
    const float* gi = gi0 + ((size_t)t * MRP + m) * G_;
    cell_body(gi, gh + (size_t)m * G_, h + (size_t)m * D_, hpack, m,
              gamma, beta, nullptr);
}

__global__ void __launch_bounds__(128)
gru_cell1(const float* __restrict__ gi1, const float* __restrict__ gh1,
          float* __restrict__ h1s, uint32_t* __restrict__ h1p,
          const float* __restrict__ gamma, const float* __restrict__ beta,
          float* __restrict__ out, int t) {
    int m = blockIdx.x;
    int b = m / N_, n = m % N_;
    float* o2 = out + ((size_t)(b * T_ + t) * N_ + n) * D_;
    cell_body(gi1 + (size_t)m * G_, gh1 + (size_t)m * G_,
              h1s + (size_t)m * D_, h1p, m, gamma + D_, beta + D_, o2);
}

// ---------------------------------------------------------------------------
__global__ void init_h_kernel(const float* __restrict__ h0,
                              float* __restrict__ h0s, float* __restrict__ h1s,
                              uint32_t* __restrict__ h0p_init,
                              uint32_t* __restrict__ h1p) {
    int row = blockIdx.x;
    int n = row % N_;
    int l = (row / N_) % 2;
    int b = row / (2 * N_);
    int tid = threadIdx.x;
    int m = b * N_ + n;
    float4 v = reinterpret_cast<const float4*>(h0 + (size_t)row * D_)[tid];
    float* hs = (l == 0) ? h0s : h1s;
    reinterpret_cast<float4*>(hs + (size_t)m * D_)[tid] = v;
    float y[4] = { v.x, v.y, v.z, v.w };
    write_packed_bf16((l == 0) ? h0p_init : h1p, m, tid * 4, y);
}

__global__ void write_hidden_kernel(const float* __restrict__ h0s,
                                    const float* __restrict__ h1s,
                                    float* __restrict__ dst) {
    int i = blockIdx.x * blockDim.x + threadIdx.x;
    if (i >= 2 * MR * D_) return;
    int d = i % D_;
    int r = i / D_;
    int n = r % N_; r /= N_;
    int l = r % 2;
    int b = r / 2;
    const float* src = (l == 0) ? h0s : h1s;
    dst[i] = src[((size_t)b * N_ + n) * D_ + d];
}

// ---------------------------------------------------------------------------
extern "C" void kernel_launch(void* const* d_in, const int* in_sizes, int n_in,
                              void* d_out, int out_size) {
    (void)in_sizes; (void)n_in;
    const float* x     = (const float*)d_in[0];
    const float* h0    = (const float*)d_in[1];
    const float* Wi    = (const float*)d_in[2];
    const float* bi    = (const float*)d_in[3];
    const float* Wh    = (const float*)d_in[4];
    const float* bh    = (const float*)d_in[5];
    const float* gamma = (const float*)d_in[6];
    const float* beta  = (const float*)d_in[7];
    float* out = (float*)d_out;

    float *gi0, *gh0, *gi1, *gh1, *h0s, *h1s;
    uint4 *h0p, *h1p, *xp, *Wp;
    cudaGetSymbolAddress((void**)&gi0, g_gi0);
    cudaGetSymbolAddress((void**)&gh0, g_gh0);
    cudaGetSymbolAddress((void**)&gi1, g_gi1);
    cudaGetSymbolAddress((void**)&gh1, g_gh1);
    cudaGetSymbolAddress((void**)&h0s, g_h0s);
    cudaGetSymbolAddress((void**)&h1s, g_h1s);
    cudaGetSymbolAddress((void**)&h0p, g_h0p);
    cudaGetSymbolAddress((void**)&h1p, g_h1p);
    cudaGetSymbolAddress((void**)&xp,  g_xp);
    cudaGetSymbolAddress((void**)&Wp,  g_Wp);

    cudaFuncSetAttribute(bf16_gemm1_kernel,
                         cudaFuncAttributeMaxDynamicSharedMemorySize, SMEM_BYTES);
    cudaFuncSetAttribute(bf16_gemm2_kernel,
                         cudaFuncAttributeMaxDynamicSharedMemorySize, SMEM_BYTES);

    static cudaStream_t s_hi = nullptr, s_L1 = nullptr, s_bg = nullptr;
    static cudaEvent_t ev_fork, ev_hi_done, ev_L1_done;
    static cudaEvent_t ev_gi0[T_], ev_h0[T_], ev_gi1[T_];
    if (!s_hi) {
        int lo = 0, hi = 0;
        cudaDeviceGetStreamPriorityRange(&lo, &hi);
        cudaStreamCreateWithPriority(&s_hi, cudaStreamNonBlocking, hi);
        cudaStreamCreateWithPriority(&s_L1, cudaStreamNonBlocking, lo);
        cudaStreamCreateWithPriority(&s_bg, cudaStreamNonBlocking, lo);
        cudaEventCreateWithFlags(&ev_fork,    cudaEventDisableTiming);
        cudaEventCreateWithFlags(&ev_hi_done, cudaEventDisableTiming);
        cudaEventCreateWithFlags(&ev_L1_done, cudaEventDisableTiming);
        for (int i = 0; i < T_; i++) {
            cudaEventCreateWithFlags(&ev_gi0[i], cudaEventDisableTiming);
            cudaEventCreateWithFlags(&ev_h0[i],  cudaEventDisableTiming);
            cudaEventCreateWithFlags(&ev_gi1[i], cudaEventDisableTiming);
        }
    }

    const uint4* Wi0p = Wp;
    const uint4* Wi1p = Wp + WQ_PER_W;
    const uint4* Wh0p = Wp + 2 * WQ_PER_W;
    const uint4* Wh1p = Wp + 3 * WQ_PER_W;
    uint4* h0pb[2] = { h0p, h0p + HQ };

    // ---- prologue on stream 0 ----
    prepack_kernel<<<dim3(CT_, NCF, 4), 256>>>(Wi, Wh, Wp);
    init_h_kernel<<<2 * MR, 128>>>(h0, h0s, h1s,
                                   (uint32_t*)h0pb[1], (uint32_t*)h1p);
    xpack_kernel<<<MB_, 128>>>(x, xp);

    cudaEventRecord(ev_fork, 0);
    cudaStreamWaitEvent(s_bg, ev_fork, 0);
    cudaStreamWaitEvent(s_hi, ev_fork, 0);

    // background: gi0 slices 1..T-1
    for (int t = 1; t < T_; t++) {
        bf16_gemm1_kernel<<<dim3(CT_, RT_R), 256, SMEM_BYTES, s_bg>>>(
            xp + (size_t)t * HQ, Wi0p, bi, gi0 + (size_t)t * MRP * G_);
        cudaEventRecord(ev_gi0[t], s_bg);
    }

    // critical chain start: gi0 slice 0, GH0(0), cell0(0)
    bf16_gemm1_kernel<<<dim3(CT_, RT_R), 256, SMEM_BYTES, s_hi>>>(
        xp, Wi0p, bi, gi0);
    bf16_gemm1_kernel<<<dim3(CT_, RT_R), 256, SMEM_BYTES, s_hi>>>(
        h0pb[1], Wh0p, bh, gh0);
    gru_cell0<<<MR, 128, 0, s_hi>>>(gi0, 0, gh0, h0s,
                                    (uint32_t*)h0pb[0], gamma, beta);
    cudaEventRecord(ev_h0[0], s_hi);

    for (int t = 0; t < T_; t++) {
        // --- layer-1 work for step t (lags on s_L1) ---
        cudaStreamWaitEvent(s_L1, ev_h0[t], 0);
        bf16_gemm2_kernel<<<dim3(CT_, RT_R, 2), 256, SMEM_BYTES, s_L1>>>(
            h0pb[t & 1], Wi1p, bi + G_, gi1,
            h1p,         Wh1p, bh + G_, gh1);
        cudaEventRecord(ev_gi1[t], s_L1);
        gru_cell1<<<MR, 128, 0, s_L1>>>(gi1, gh1, h1s, (uint32_t*)h1p,
                                        gamma, beta, out, t);

        // --- layer-0 critical chain: produce cell0(t+1) ---
        if (t < T_ - 1) {
            bf16_gemm1_kernel<<<dim3(CT_, RT_R), 256, SMEM_BYTES, s_hi>>>(
                h0pb[t & 1], Wh0p, bh, gh0);
            cudaStreamWaitEvent(s_hi, ev_gi0[t + 1], 0);
            if (t >= 1)
                cudaStreamWaitEvent(s_hi, ev_gi1[t - 1], 0);  // h0p reuse safety
            gru_cell0<<<MR, 128, 0, s_hi>>>(gi0, t + 1, gh0, h0s,
                                            (uint32_t*)h0pb[(t + 1) & 1],
                                            gamma, beta);
            cudaEventRecord(ev_h0[t + 1], s_hi);
        }
    }

    cudaEventRecord(ev_hi_done, s_hi);
    cudaEventRecord(ev_L1_done, s_L1);
    cudaStreamWaitEvent(0, ev_hi_done, 0);
    cudaStreamWaitEvent(0, ev_L1_done, 0);

    long long need = (long long)MB_ * D_ + (long long)2 * MR * D_;
    if ((long long)out_size >= need) {
        int tot = 2 * MR * D_;
        write_hidden_kernel<<<(tot + 255) / 256, 256>>>(h0s, h1s,
                                                        out + (size_t)MB_ * D_);
    }
}

// round 13
// speedup vs baseline: 1.0326x; 1.0326x over previous
#include <cuda_runtime.h>
#include <cuda_bf16.h>
#include <math.h>
#include <stdint.h>

// GraphRNN: 2-layer LayerNorm-GRU scan. B=16, T=24, N=207, D=512, G=1536.
// R13: R11 structure (bf16-k16 3x-split, BK=16, 128x64 tiles @ 3 CTAs/SM,
//      3-stream dataflow) with a 4-stage cp.async pipeline (wait_group 2).
namespace {
constexpr int B_ = 16, T_ = 24, N_ = 207, D_ = 512, G_ = 1536;
constexpr int MR  = B_ * N_;        // 3312 rows per timestep
constexpr int MRP = 3328;           // padded: 26*128
constexpr int MB_ = B_ * T_ * N_;   // 79488

constexpr int BK = 16;              // k-chunk (one k16 MMA per chunk)
constexpr int NCHUNK = D_ / BK;     // 32
constexpr int CT_ = G_ / 64;        // 24 col-tiles of 64
constexpr int RT_R = MRP / 128;     // 26 row-tiles per timestep

constexpr int A_Q = 512, B_Q = 256;
constexpr int STAGE_Q = A_Q + B_Q;  // 768 quads = 12KB
constexpr int STAGES = 4;
constexpr int SMEM_BYTES = STAGES * STAGE_Q * 16;  // 49152

constexpr size_t WQ_PER_W = (size_t)CT_ * NCHUNK * B_Q;   // 196608
constexpr size_t HQ  = (size_t)RT_R * NCHUNK * A_Q;       // packed rows / t
constexpr size_t XQ  = (size_t)T_ * HQ;
}

// ---------------- scratch (device globals; zero-initialized) ----------------
__device__ float g_gi0[(size_t)T_ * MRP * G_];   // t-major
__device__ float g_gh0[(size_t)MRP * G_];
__device__ float g_gi1[(size_t)MRP * G_];
__device__ float g_gh1[(size_t)MRP * G_];
__device__ float g_h0s[(size_t)MRP * D_];
__device__ float g_h1s[(size_t)MRP * D_];
__device__ uint4 g_h0p[2 * HQ];                  // double-buffered (parity t&1)
__device__ uint4 g_h1p[HQ];
__device__ uint4 g_xp[XQ];                       // t-major packed x
__device__ uint4 g_Wp[4 * WQ_PER_W];

// ---------------- helpers ----------------
__device__ __forceinline__ uint32_t smem_u32(const void* p) {
    uint32_t a;
    asm("{ .reg .u64 t; cvta.to.shared.u64 t, %1; cvt.u32.u64 %0, t; }"
        : "=r"(a) : "l"(p));
    return a;
}
#define CP_ASYNC16(dst, src) \
    asm volatile("cp.async.cg.shared.global [%0], [%1], 16;" :: "r"(dst), "l"(src))
#define CP_COMMIT() asm volatile("cp.async.commit_group;" ::: "memory")
template <int N>
__device__ __forceinline__ void cp_wait() {
    asm volatile("cp.async.wait_group %0;" :: "n"(N) : "memory");
}

// bf16 hi/lo split of a float
__device__ __forceinline__ void split_bf16(float x, uint16_t& hi, uint16_t& lo) {
    __nv_bfloat16 h = __float2bfloat16_rn(x);
    float hf = __bfloat162float(h);
    __nv_bfloat16 l = __float2bfloat16_rn(x - hf);
    hi = *reinterpret_cast<uint16_t*>(&h);
    lo = *reinterpret_cast<uint16_t*>(&l);
}
__device__ __forceinline__ uint32_t pack2(uint16_t a, uint16_t b) {
    return (uint32_t)a | ((uint32_t)b << 16);
}

#define MMA_BF16(d, a, b0, b1)                                              \
    asm volatile("mma.sync.aligned.m16n8k16.row.col.f32.bf16.bf16.f32 "     \
        "{%0,%1,%2,%3}, {%4,%5,%6,%7}, {%8,%9}, {%0,%1,%2,%3};"             \
        : "+f"((d)[0]), "+f"((d)[1]), "+f"((d)[2]), "+f"((d)[3])            \
        : "r"((a)[0]), "r"((a)[1]), "r"((a)[2]), "r"((a)[3]),               \
          "r"(b0), "r"(b1))

// ---------------------------------------------------------------------------
// Packed-activation writer (layout unchanged from R11).
// ---------------------------------------------------------------------------
__device__ __forceinline__ void write_packed_bf16(uint32_t* Ap, int m, int d0,
                                                  const float* y) {
    int rt = m >> 7, mrow = m & 127;
    int mg = mrow >> 4, rr = mrow & 15;
    int ch = d0 >> 4, kd = d0 & 15;
    int khalf = kd >> 3;
    int tgb = (kd & 7) >> 1;
    int s = (rr >> 3) + 2 * khalf;
    size_t base = ((size_t)rt * NCHUNK + ch) * A_Q;
    uint16_t h0, l0, h1, l1;
#pragma unroll
    for (int j = 0; j < 2; j++) {
        split_bf16(y[2 * j],     h0, l0);
        split_bf16(y[2 * j + 1], h1, l1);
        int lane = (rr & 7) * 4 + tgb + j;
        size_t qhi = base + (size_t)mg * 32 + lane;
        Ap[qhi * 4 + s]         = pack2(h0, h1);
        Ap[(qhi + 256) * 4 + s] = pack2(l0, l1);
    }
}

// ---------------------------------------------------------------------------
// GEMM core (128x64 C tile), pure LDS.128 + bf16 k16 HMMA, 4-stage pipeline.
// ---------------------------------------------------------------------------
__device__ __forceinline__ void load_stage(uint32_t sS, const uint4* __restrict__ Aq,
                                           const uint4* __restrict__ Bq,
                                           int ch, int tid) {
    const uint4* a = Aq + (size_t)ch * A_Q;
    const uint4* b = Bq + (size_t)ch * B_Q;
#pragma unroll
    for (int i = 0; i < 2; i++) {
        int s = tid + i * 256;
        CP_ASYNC16(sS + (uint32_t)s * 16u, a + s);
    }
    CP_ASYNC16(sS + (uint32_t)(A_Q + tid) * 16u, b + tid);
}

__device__ __forceinline__ void bf16_gemm_core(const uint4* __restrict__ Ap,
                                               const uint4* __restrict__ Wp,
                                               const float* __restrict__ bias,
                                               float* __restrict__ C) {
    extern __shared__ uint4 smq[];

    const int tid  = threadIdx.x;
    const int lane = tid & 31, warp = tid >> 5;
    const int warpM = warp & 3, warpN = warp >> 2;
    const int r  = lane >> 2;
    const int qk = lane & 3;

    const uint4* Aq = Ap + (size_t)blockIdx.y * (NCHUNK * A_Q);
    const uint4* Bq = Wp + (size_t)blockIdx.x * (NCHUNK * B_Q);

    float acc[2][4][4];
#pragma unroll
    for (int mt = 0; mt < 2; mt++)
#pragma unroll
        for (int nt = 0; nt < 4; nt++)
#pragma unroll
            for (int i = 0; i < 4; i++) acc[mt][nt][i] = 0.f;

    uint32_t sb = smem_u32(smq);
    load_stage(sb,                    Aq, Bq, 0, tid); CP_COMMIT();
    load_stage(sb + 1 * STAGE_Q * 16, Aq, Bq, 1, tid); CP_COMMIT();
    load_stage(sb + 2 * STAGE_Q * 16, Aq, Bq, 2, tid); CP_COMMIT();

    for (int ch = 0; ch < NCHUNK; ch++) {
        // wait for chunk ch's group (keep up to 2 newer groups in flight)
        if (ch <= NCHUNK - 3)      cp_wait<2>();
        else if (ch == NCHUNK - 2) cp_wait<1>();
        else                       cp_wait<0>();
        __syncthreads();
        if (ch + 3 < NCHUNK) {
            load_stage(sb + ((ch + 3) % STAGES) * (STAGE_Q * 16), Aq, Bq, ch + 3, tid);
            CP_COMMIT();
        }
        const uint4* As = smq + (size_t)(ch % STAGES) * STAGE_Q;
        const uint4* Bs = As + A_Q;

        uint4 ah[2], al[2];
#pragma unroll
        for (int mt = 0; mt < 2; mt++) {
            int mg = warpM * 2 + mt;
            ah[mt] = As[mg * 32 + lane];
            al[mt] = As[mg * 32 + lane + 256];
        }
        uint4 bf[4];
#pragma unroll
        for (int j = 0; j < 4; j++) {
            int g = warpN * 4 + j;
            bf[j] = Bs[g * 32 + lane];
        }
        // pass 1: al * bh
#pragma unroll
        for (int j = 0; j < 4; j++)
#pragma unroll
            for (int mt = 0; mt < 2; mt++)
                MMA_BF16(acc[mt][j], ((const uint32_t*)&al[mt]),
                         bf[j].x, bf[j].y);
        // pass 2: ah * bl
#pragma unroll
        for (int j = 0; j < 4; j++)
#pragma unroll
            for (int mt = 0; mt < 2; mt++)
                MMA_BF16(acc[mt][j], ((const uint32_t*)&ah[mt]),
                         bf[j].z, bf[j].w);
        // pass 3: ah * bh
#pragma unroll
        for (int j = 0; j < 4; j++)
#pragma unroll
            for (int mt = 0; mt < 2; mt++)
                MMA_BF16(acc[mt][j], ((const uint32_t*)&ah[mt]),
                         bf[j].x, bf[j].y);
    }

    const int brow = blockIdx.y * 128;
    const int bcol = blockIdx.x * 64;
    const int q2 = qk * 2;
#pragma unroll
    for (int mt = 0; mt < 2; mt++) {
        const int row0 = brow + warpM * 32 + mt * 16 + r;
#pragma unroll
        for (int nt = 0; nt < 4; nt++) {
            const int col = bcol + warpN * 32 + nt * 8 + q2;
            const float2 bv = *reinterpret_cast<const float2*>(bias + col);
            float2 v0 = make_float2(acc[mt][nt][0] + bv.x, acc[mt][nt][1] + bv.y);
            float2 v1 = make_float2(acc[mt][nt][2] + bv.x, acc[mt][nt][3] + bv.y);
            *reinterpret_cast<float2*>(C + (size_t)row0 * G_ + col) = v0;
            *reinterpret_cast<float2*>(C + (size_t)(row0 + 8) * G_ + col) = v1;
        }
    }
}

__global__ void __launch_bounds__(256, 3)
bf16_gemm1_kernel(const uint4* __restrict__ Ap, const uint4* __restrict__ Wp,
                  const float* __restrict__ bias, float* __restrict__ C) {
    bf16_gemm_core(Ap, Wp, bias, C);
}

__global__ void __launch_bounds__(256, 3)
bf16_gemm2_kernel(const uint4* A0, const uint4* P0, const float* b0, float* C0,
                  const uint4* A1, const uint4* P1, const float* b1, float* C1) {
    const uint4* A; const uint4* P; const float* bias; float* C;
    if (blockIdx.z == 0) { A = A0; P = P0; bias = b0; C = C0; }
    else                 { A = A1; P = P1; bias = b1; C = C1; }
    bf16_gemm_core(A, P, bias, C);
}

// ---------------------------------------------------------------------------
// Weight prepack (unchanged from R11).
// ---------------------------------------------------------------------------
__global__ void prepack_kernel(const float* __restrict__ Wi,
                               const float* __restrict__ Wh,
                               uint4* __restrict__ Wp) {
    __shared__ float tile[16][64];
    const int ct = blockIdx.x, ch = blockIdx.y, z = blockIdx.z;
    const float* src = (z < 2 ? Wi : Wh) + (size_t)(z & 1) * D_ * G_;
    const int tid = threadIdx.x;

#pragma unroll
    for (int i = 0; i < 4; i++) {
        int s = tid + i * 256;
        int kk = s >> 6, n = s & 63;
        tile[kk][n] = src[(size_t)(ch * BK + kk) * G_ + ct * 64 + n];
    }
    __syncthreads();

    uint4* dst = Wp + ((size_t)z * CT_ + ct) * (NCHUNK * B_Q) + (size_t)ch * B_Q;
    if (tid < 256) {
        int lane = tid & 31, g = tid >> 5;
        int nl = g * 8 + (lane >> 2);
        int tg = lane & 3;
        uint16_t h0a, l0a, h0b, l0b, h1a, l1a, h1b, l1b;
        split_bf16(tile[2 * tg][nl],     h0a, l0a);
        split_bf16(tile[2 * tg + 1][nl], h0b, l0b);
        split_bf16(tile[2 * tg + 8][nl], h1a, l1a);
        split_bf16(tile[2 * tg + 9][nl], h1b, l1b);
        uint4 q;
        q.x = pack2(h0a, h0b);
        q.y = pack2(h1a, h1b);
        q.z = pack2(l0a, l0b);
        q.w = pack2(l1a, l1b);
        dst[tid] = q;
    }
}

// ---------------------------------------------------------------------------
// x prepack: x row (b,t,n) -> t-major packed row t*MRP + b*N + n
// ---------------------------------------------------------------------------
__global__ void xpack_kernel(const float* __restrict__ x, uint4* __restrict__ xp) {
    int min_ = blockIdx.x;
    int n = min_ % N_;
    int t = (min_ / N_) % T_;
    int b = min_ / (N_ * T_);
    int m = t * MRP + b * N_ + n;
    int tid = threadIdx.x;
    float4 v = reinterpret_cast<const float4*>(x + (size_t)min_ * D_)[tid];
    float y[4] = { v.x, v.y, v.z, v.w };
    write_packed_bf16((uint32_t*)xp, m, tid * 4, y);
}

// ---------------------------------------------------------------------------
// Fused GRU cell + LayerNorm
// ---------------------------------------------------------------------------
__device__ __forceinline__ float sigf(float v) { return 1.f / (1.f + expf(-v)); }

__device__ __forceinline__ void cell_body(const float* __restrict__ gi,
                                          const float* __restrict__ ghrow,
                                          float* __restrict__ hrow,
                                          uint32_t* __restrict__ hpack, int m,
                                          const float* __restrict__ gamma,
                                          const float* __restrict__ beta,
                                          float* __restrict__ o2) {
    const float4* gi4 = reinterpret_cast<const float4*>(gi);
    const float4* gh4 = reinterpret_cast<const float4*>(ghrow);
    float4* h4 = reinterpret_cast<float4*>(hrow);
    int tid = threadIdx.x;

    float4 ir = gi4[tid], iz = gi4[128 + tid], inn = gi4[256 + tid];
    float4 hr = gh4[tid], hz = gh4[128 + tid], hn = gh4[256 + tid];
    float4 hv = h4[tid];

    float o[4];
    {
        float rr, z, nv;
        rr = sigf(ir.x + hr.x); z = sigf(iz.x + hz.x); nv = tanhf(inn.x + rr * hn.x);
        o[0] = nv + z * (hv.x - nv);
        rr = sigf(ir.y + hr.y); z = sigf(iz.y + hz.y); nv = tanhf(inn.y + rr * hn.y);
        o[1] = nv + z * (hv.y - nv);
        rr = sigf(ir.z + hr.z); z = sigf(iz.z + hz.z); nv = tanhf(inn.z + rr * hn.z);
        o[2] = nv + z * (hv.z - nv);
        rr = sigf(ir.w + hr.w); z = sigf(iz.w + hz.w); nv = tanhf(inn.w + rr * hn.w);
        o[3] = nv + z * (hv.w - nv);
    }
    float s = o[0] + o[1] + o[2] + o[3];
    float s2 = o[0]*o[0] + o[1]*o[1] + o[2]*o[2] + o[3]*o[3];
#pragma unroll
    for (int off = 16; off > 0; off >>= 1) {
        s  += __shfl_xor_sync(0xffffffffu, s,  off);
        s2 += __shfl_xor_sync(0xffffffffu, s2, off);
    }
    __shared__ float sh[4], sh2[4];
    int w = tid >> 5;
    if ((tid & 31) == 0) { sh[w] = s; sh2[w] = s2; }
    __syncthreads();
    s  = sh[0]  + sh[1]  + sh[2]  + sh[3];
    s2 = sh2[0] + sh2[1] + sh2[2] + sh2[3];
    float mu  = s * (1.f / D_);
    float var = s2 * (1.f / D_) - mu * mu;
    float inv = rsqrtf(var + 1e-5f);

    const float4 g4 = reinterpret_cast<const float4*>(gamma)[tid];
    const float4 b4 = reinterpret_cast<const float4*>(beta)[tid];
    float y[4];
    y[0] = (o[0] - mu) * inv * g4.x + b4.x;
    y[1] = (o[1] - mu) * inv * g4.y + b4.y;
    y[2] = (o[2] - mu) * inv * g4.z + b4.z;
    y[3] = (o[3] - mu) * inv * g4.w + b4.w;
    h4[tid] = make_float4(y[0], y[1], y[2], y[3]);
    write_packed_bf16(hpack, m, tid * 4, y);
    if (o2) reinterpret_cast<float4*>(o2)[tid] =
        make_float4(y[0], y[1], y[2], y[3]);
}

__global__ void __launch_bounds__(128)
gru_cell0(const float* __restrict__ gi0, int t,
          const float* __restrict__ gh, float* __restrict__ h,
          uint32_t* __restrict__ hpack,
          const float* __restrict__ gamma, const float* __restrict__ beta) {
    int m = blockIdx.x;
    const float* gi = gi0 + ((size_t)t * MRP + m) * G_;
    cell_body(gi, gh + (size_t)m * G_, h + (size_t)m * D_, hpack, m,
              gamma, beta, nullptr);
}

__global__ void __launch_bounds__(128)
gru_cell1(const float* __restrict__ gi1, const float* __restrict__ gh1,
          float* __restrict__ h1s, uint32_t* __restrict__ h1p,
          const float* __restrict__ gamma, const float* __restrict__ beta,
          float* __restrict__ out, int t) {
    int m = blockIdx.x;
    int b = m / N_, n = m % N_;
    float* o2 = out + ((size_t)(b * T_ + t) * N_ + n) * D_;
    cell_body(gi1 + (size_t)m * G_, gh1 + (size_t)m * G_,
              h1s + (size_t)m * D_, h1p, m, gamma + D_, beta + D_, o2);
}

// ---------------------------------------------------------------------------
__global__ void init_h_kernel(const float* __restrict__ h0,
                              float* __restrict__ h0s, float* __restrict__ h1s,
                              uint32_t* __restrict__ h0p_init,
                              uint32_t* __restrict__ h1p) {
    int row = blockIdx.x;
    int n = row % N_;
    int l = (row / N_) % 2;
    int b = row / (2 * N_);
    int tid = threadIdx.x;
    int m = b * N_ + n;
    float4 v = reinterpret_cast<const float4*>(h0 + (size_t)row * D_)[tid];
    float* hs = (l == 0) ? h0s : h1s;
    reinterpret_cast<float4*>(hs + (size_t)m * D_)[tid] = v;
    float y[4] = { v.x, v.y, v.z, v.w };
    write_packed_bf16((l == 0) ? h0p_init : h1p, m, tid * 4, y);
}

__global__ void write_hidden_kernel(const float* __restrict__ h0s,
                                    const float* __restrict__ h1s,
                                    float* __restrict__ dst) {
    int i = blockIdx.x * blockDim.x + threadIdx.x;
    if (i >= 2 * MR * D_) return;
    int d = i % D_;
    int r = i / D_;
    int n = r % N_; r /= N_;
    int l = r % 2;
    int b = r / 2;
    const float* src = (l == 0) ? h0s : h1s;
    dst[i] = src[((size_t)b * N_ + n) * D_ + d];
}

// ---------------------------------------------------------------------------
extern "C" void kernel_launch(void* const* d_in, const int* in_sizes, int n_in,
                              void* d_out, int out_size) {
    (void)in_sizes; (void)n_in;
    const float* x     = (const float*)d_in[0];
    const float* h0    = (const float*)d_in[1];
    const float* Wi    = (const float*)d_in[2];
    const float* bi    = (const float*)d_in[3];
    const float* Wh    = (const float*)d_in[4];
    const float* bh    = (const float*)d_in[5];
    const float* gamma = (const float*)d_in[6];
    const float* beta  = (const float*)d_in[7];
    float* out = (float*)d_out;

    float *gi0, *gh0, *gi1, *gh1, *h0s, *h1s;
    uint4 *h0p, *h1p, *xp, *Wp;
    cudaGetSymbolAddress((void**)&gi0, g_gi0);
    cudaGetSymbolAddress((void**)&gh0, g_gh0);
    cudaGetSymbolAddress((void**)&gi1, g_gi1);
    cudaGetSymbolAddress((void**)&gh1, g_gh1);
    cudaGetSymbolAddress((void**)&h0s, g_h0s);
    cudaGetSymbolAddress((void**)&h1s, g_h1s);
    cudaGetSymbolAddress((void**)&h0p, g_h0p);
    cudaGetSymbolAddress((void**)&h1p, g_h1p);
    cudaGetSymbolAddress((void**)&xp,  g_xp);
    cudaGetSymbolAddress((void**)&Wp,  g_Wp);

    cudaFuncSetAttribute(bf16_gemm1_kernel,
                         cudaFuncAttributeMaxDynamicSharedMemorySize, SMEM_BYTES);
    cudaFuncSetAttribute(bf16_gemm2_kernel,
                         cudaFuncAttributeMaxDynamicSharedMemorySize, SMEM_BYTES);

    static cudaStream_t s_hi = nullptr, s_L1 = nullptr, s_bg = nullptr;
    static cudaEvent_t ev_fork, ev_hi_done, ev_L1_done;
    static cudaEvent_t ev_gi0[T_], ev_h0[T_], ev_gi1[T_];
    if (!s_hi) {
        int lo = 0, hi = 0;
        cudaDeviceGetStreamPriorityRange(&lo, &hi);
        cudaStreamCreateWithPriority(&s_hi, cudaStreamNonBlocking, hi);
        cudaStreamCreateWithPriority(&s_L1, cudaStreamNonBlocking, lo);
        cudaStreamCreateWithPriority(&s_bg, cudaStreamNonBlocking, lo);
        cudaEventCreateWithFlags(&ev_fork,    cudaEventDisableTiming);
        cudaEventCreateWithFlags(&ev_hi_done, cudaEventDisableTiming);
        cudaEventCreateWithFlags(&ev_L1_done, cudaEventDisableTiming);
        for (int i = 0; i < T_; i++) {
            cudaEventCreateWithFlags(&ev_gi0[i], cudaEventDisableTiming);
            cudaEventCreateWithFlags(&ev_h0[i],  cudaEventDisableTiming);
            cudaEventCreateWithFlags(&ev_gi1[i], cudaEventDisableTiming);
        }
    }

    const uint4* Wi0p = Wp;
    const uint4* Wi1p = Wp + WQ_PER_W;
    const uint4* Wh0p = Wp + 2 * WQ_PER_W;
    const uint4* Wh1p = Wp + 3 * WQ_PER_W;
    uint4* h0pb[2] = { h0p, h0p + HQ };

    // ---- prologue on stream 0 ----
    prepack_kernel<<<dim3(CT_, NCHUNK, 4), 256>>>(Wi, Wh, Wp);
    init_h_kernel<<<2 * MR, 128>>>(h0, h0s, h1s,
                                   (uint32_t*)h0pb[1], (uint32_t*)h1p);
    xpack_kernel<<<MB_, 128>>>(x, xp);

    cudaEventRecord(ev_fork, 0);
    cudaStreamWaitEvent(s_bg, ev_fork, 0);
    cudaStreamWaitEvent(s_hi, ev_fork, 0);

    // background: gi0 slices 1..T-1
    for (int t = 1; t < T_; t++) {
        bf16_gemm1_kernel<<<dim3(CT_, RT_R), 256, SMEM_BYTES, s_bg>>>(
            xp + (size_t)t * HQ, Wi0p, bi, gi0 + (size_t)t * MRP * G_);
        cudaEventRecord(ev_gi0[t], s_bg);
    }

    // critical chain start: gi0 slice 0, GH0(0), cell0(0)
    bf16_gemm1_kernel<<<dim3(CT_, RT_R), 256, SMEM_BYTES, s_hi>>>(
        xp, Wi0p, bi, gi0);
    bf16_gemm1_kernel<<<dim3(CT_, RT_R), 256, SMEM_BYTES, s_hi>>>(
        h0pb[1], Wh0p, bh, gh0);
    gru_cell0<<<MR, 128, 0, s_hi>>>(gi0, 0, gh0, h0s,
                                    (uint32_t*)h0pb[0], gamma, beta);
    cudaEventRecord(ev_h0[0], s_hi);

    for (int t = 0; t < T_; t++) {
        // --- layer-1 work for step t (lags on s_L1) ---
        cudaStreamWaitEvent(s_L1, ev_h0[t], 0);
        bf16_gemm2_kernel<<<dim3(CT_, RT_R, 2), 256, SMEM_BYTES, s_L1>>>(
            h0pb[t & 1], Wi1p, bi + G_, gi1,
            h1p,         Wh1p, bh + G_, gh1);
        cudaEventRecord(ev_gi1[t], s_L1);
        gru_cell1<<<MR, 128, 0, s_L1>>>(gi1, gh1, h1s, (uint32_t*)h1p,
                                        gamma, beta, out, t);

        // --- layer-0 critical chain: produce cell0(t+1) ---
        if (t < T_ - 1) {
            bf16_gemm1_kernel<<<dim3(CT_, RT_R), 256, SMEM_BYTES, s_hi>>>(
                h0pb[t & 1], Wh0p, bh, gh0);
            cudaStreamWaitEvent(s_hi, ev_gi0[t + 1], 0);
            if (t >= 1)
                cudaStreamWaitEvent(s_hi, ev_gi1[t - 1], 0);  // h0p reuse safety
            gru_cell0<<<MR, 128, 0, s_hi>>>(gi0, t + 1, gh0, h0s,
                                            (uint32_t*)h0pb[(t + 1) & 1],
                                            gamma, beta);
            cudaEventRecord(ev_h0[t + 1], s_hi);
        }
    }

    cudaEventRecord(ev_hi_done, s_hi);
    cudaEventRecord(ev_L1_done, s_L1);
    cudaStreamWaitEvent(0, ev_hi_done, 0);
    cudaStreamWaitEvent(0, ev_L1_done, 0);

    long long need = (long long)MB_ * D_ + (long long)2 * MR * D_;
    if ((long long)out_size >= need) {
        int tot = 2 * MR * D_;
        write_hidden_kernel<<<(tot + 255) / 256, 256>>>(h0s, h1s,
                                                        out + (size_t)MB_ * D_);
    }
}

// round 14
// speedup vs baseline: 1.3214x; 1.2796x over previous
#include <cuda_runtime.h>
#include <cuda_fp16.h>
#include <math.h>
#include <stdint.h>

// GraphRNN: 2-layer LayerNorm-GRU scan. B=16, T=24, N=207, D=512, G=1536.
// R14: asymmetric fp16 2-pass GEMM: A split hi/lo (exact to 2^-22), B single
//      fp16 (only error source, ~1.4e-4 RMS). 2 HMMA passes instead of 3.
//      BK=16, 3 stages, 128x64 tiles @ 3 CTAs/SM, R11 3-stream dataflow.
namespace {
constexpr int B_ = 16, T_ = 24, N_ = 207, D_ = 512, G_ = 1536;
constexpr int MR  = B_ * N_;        // 3312 rows per timestep
constexpr int MRP = 3328;           // padded: 26*128
constexpr int MB_ = B_ * T_ * N_;   // 79488

constexpr int BK = 16;              // k-chunk (one k16 MMA per chunk)
constexpr int NCHUNK = D_ / BK;     // 32
constexpr int CT_ = G_ / 64;        // 24 col-tiles of 64
constexpr int RT_R = MRP / 128;     // 26 row-tiles per timestep

// A per (rowtile, chunk): 256 hi quads + 256 lo quads = 8KB
// B per (coltile64, chunk): 8 g * 32 lanes uint2 = 2KB
constexpr int A_Q = 512;            // uint4 units
constexpr int B_U2 = 256;           // uint2 units
constexpr int STAGE_BYTES = A_Q * 16 + B_U2 * 8;   // 10240
constexpr int STAGES = 3;
constexpr int SMEM_BYTES = STAGES * STAGE_BYTES;   // 30720

constexpr size_t WU2_PER_W = (size_t)CT_ * NCHUNK * B_U2;  // uint2 units
constexpr size_t HQ  = (size_t)RT_R * NCHUNK * A_Q;        // packed rows / t
constexpr size_t XQ  = (size_t)T_ * HQ;
}

// ---------------- scratch (device globals; zero-initialized) ----------------
__device__ float g_gi0[(size_t)T_ * MRP * G_];   // t-major
__device__ float g_gh0[(size_t)MRP * G_];
__device__ float g_gi1[(size_t)MRP * G_];
__device__ float g_gh1[(size_t)MRP * G_];
__device__ float g_h0s[(size_t)MRP * D_];
__device__ float g_h1s[(size_t)MRP * D_];
__device__ uint4 g_h0p[2 * HQ];                  // double-buffered (parity t&1)
__device__ uint4 g_h1p[HQ];
__device__ uint4 g_xp[XQ];                       // t-major packed x
__device__ uint2 g_Wp[4 * WU2_PER_W];            // fp16 weights, frag-packed

// ---------------- helpers ----------------
__device__ __forceinline__ uint32_t smem_u32(const void* p) {
    uint32_t a;
    asm("{ .reg .u64 t; cvta.to.shared.u64 t, %1; cvt.u32.u64 %0, t; }"
        : "=r"(a) : "l"(p));
    return a;
}
#define CP_ASYNC16(dst, src) \
    asm volatile("cp.async.cg.shared.global [%0], [%1], 16;" :: "r"(dst), "l"(src))
#define CP_ASYNC8(dst, src) \
    asm volatile("cp.async.ca.shared.global [%0], [%1], 8;" :: "r"(dst), "l"(src))
#define CP_COMMIT() asm volatile("cp.async.commit_group;" ::: "memory")
template <int N>
__device__ __forceinline__ void cp_wait() {
    asm volatile("cp.async.wait_group %0;" :: "n"(N) : "memory");
}

// fp16 hi/lo split of a float (hi+lo represents x to ~2^-22)
__device__ __forceinline__ void split_fp16(float x, uint16_t& hi, uint16_t& lo) {
    __half h = __float2half_rn(x);
    float hf = __half2float(h);
    __half l = __float2half_rn(x - hf);
    hi = *reinterpret_cast<uint16_t*>(&h);
    lo = *reinterpret_cast<uint16_t*>(&l);
}
__device__ __forceinline__ uint16_t f2h(float x) {
    __half h = __float2half_rn(x);
    return *reinterpret_cast<uint16_t*>(&h);
}
__device__ __forceinline__ uint32_t pack2(uint16_t a, uint16_t b) {
    return (uint32_t)a | ((uint32_t)b << 16);
}

#define MMA_F16(d, a, b0, b1)                                               \
    asm volatile("mma.sync.aligned.m16n8k16.row.col.f32.f16.f16.f32 "       \
        "{%0,%1,%2,%3}, {%4,%5,%6,%7}, {%8,%9}, {%0,%1,%2,%3};"             \
        : "+f"((d)[0]), "+f"((d)[1]), "+f"((d)[2]), "+f"((d)[3])            \
        : "r"((a)[0]), "r"((a)[1]), "r"((a)[2]), "r"((a)[3]),               \
          "r"(b0), "r"(b1))

// ---------------------------------------------------------------------------
// Packed-activation writer: same fragment indexing as R11, fp16 values.
// A layout per (rowtile rt, chunk ch): 512 quads, hi at mg*32+lane, lo +256.
// ---------------------------------------------------------------------------
__device__ __forceinline__ void write_packed_fp16(uint32_t* Ap, int m, int d0,
                                                  const float* y) {
    int rt = m >> 7, mrow = m & 127;
    int mg = mrow >> 4, rr = mrow & 15;
    int ch = d0 >> 4, kd = d0 & 15;
    int khalf = kd >> 3;
    int tgb = (kd & 7) >> 1;
    int s = (rr >> 3) + 2 * khalf;
    size_t base = ((size_t)rt * NCHUNK + ch) * A_Q;
    uint16_t h0, l0, h1, l1;
#pragma unroll
    for (int j = 0; j < 2; j++) {
        split_fp16(y[2 * j],     h0, l0);
        split_fp16(y[2 * j + 1], h1, l1);
        int lane = (rr & 7) * 4 + tgb + j;
        size_t qhi = base + (size_t)mg * 32 + lane;
        Ap[qhi * 4 + s]         = pack2(h0, h1);
        Ap[(qhi + 256) * 4 + s] = pack2(l0, l1);
    }
}

// ---------------------------------------------------------------------------
// GEMM core (128x64 C tile): 2-pass fp16 (ah+al)*bh. Pure LDS + HMMA.
// 256 thr, 8 warps (warpM 0..3 x warpN 0..1, 32 cols each).
// ---------------------------------------------------------------------------
__device__ __forceinline__ void load_stage(uint32_t sS, const uint4* __restrict__ Aq,
                                           const uint2* __restrict__ Bq,
                                           int ch, int tid) {
    const uint4* a = Aq + (size_t)ch * A_Q;
    const uint2* b = Bq + (size_t)ch * B_U2;
#pragma unroll
    for (int i = 0; i < 2; i++) {
        int s = tid + i * 256;
        CP_ASYNC16(sS + (uint32_t)s * 16u, a + s);
    }
    CP_ASYNC8(sS + (uint32_t)A_Q * 16u + (uint32_t)tid * 8u, b + tid);
}

__device__ __forceinline__ void f16_gemm_core(const uint4* __restrict__ Ap,
                                              const uint2* __restrict__ Wp,
                                              const float* __restrict__ bias,
                                              float* __restrict__ C) {
    extern __shared__ char smraw[];
    const int tid  = threadIdx.x;
    const int lane = tid & 31, warp = tid >> 5;
    const int warpM = warp & 3, warpN = warp >> 2;
    const int r  = lane >> 2;
    const int qk = lane & 3;

    const uint4* Aq = Ap + (size_t)blockIdx.y * (NCHUNK * A_Q);
    const uint2* Bq = Wp + (size_t)blockIdx.x * (NCHUNK * B_U2);

    float acc[2][4][4];
#pragma unroll
    for (int mt = 0; mt < 2; mt++)
#pragma unroll
        for (int nt = 0; nt < 4; nt++)
#pragma unroll
            for (int i = 0; i < 4; i++) acc[mt][nt][i] = 0.f;

    uint32_t sb = smem_u32(smraw);
    load_stage(sb,               Aq, Bq, 0, tid); CP_COMMIT();
    load_stage(sb + STAGE_BYTES, Aq, Bq, 1, tid); CP_COMMIT();

    for (int ch = 0; ch < NCHUNK; ch++) {
        if (ch < NCHUNK - 1) cp_wait<1>(); else cp_wait<0>();
        __syncthreads();
        if (ch + 2 < NCHUNK) {
            load_stage(sb + ((ch + 2) % STAGES) * STAGE_BYTES, Aq, Bq, ch + 2, tid);
            CP_COMMIT();
        }
        const char* St = smraw + (size_t)(ch % STAGES) * STAGE_BYTES;
        const uint4* As = reinterpret_cast<const uint4*>(St);
        const uint2* Bs = reinterpret_cast<const uint2*>(St + A_Q * 16);

        uint4 ah[2], al[2];
#pragma unroll
        for (int mt = 0; mt < 2; mt++) {
            int mg = warpM * 2 + mt;
            ah[mt] = As[mg * 32 + lane];
            al[mt] = As[mg * 32 + lane + 256];
        }
        uint2 bf[4];
#pragma unroll
        for (int j = 0; j < 4; j++) {
            int g = warpN * 4 + j;
            bf[j] = Bs[g * 32 + lane];
        }
        // pass 1: al * bh
#pragma unroll
        for (int j = 0; j < 4; j++)
#pragma unroll
            for (int mt = 0; mt < 2; mt++)
                MMA_F16(acc[mt][j], ((const uint32_t*)&al[mt]),
                        bf[j].x, bf[j].y);
        // pass 2: ah * bh
#pragma unroll
        for (int j = 0; j < 4; j++)
#pragma unroll
            for (int mt = 0; mt < 2; mt++)
                MMA_F16(acc[mt][j], ((const uint32_t*)&ah[mt]),
                        bf[j].x, bf[j].y);
    }

    const int brow = blockIdx.y * 128;
    const int bcol = blockIdx.x * 64;
    const int q2 = qk * 2;
#pragma unroll
    for (int mt = 0; mt < 2; mt++) {
        const int row0 = brow + warpM * 32 + mt * 16 + r;
#pragma unroll
        for (int nt = 0; nt < 4; nt++) {
            const int col = bcol + warpN * 32 + nt * 8 + q2;
            const float2 bv = *reinterpret_cast<const float2*>(bias + col);
            float2 v0 = make_float2(acc[mt][nt][0] + bv.x, acc[mt][nt][1] + bv.y);
            float2 v1 = make_float2(acc[mt][nt][2] + bv.x, acc[mt][nt][3] + bv.y);
            *reinterpret_cast<float2*>(C + (size_t)row0 * G_ + col) = v0;
            *reinterpret_cast<float2*>(C + (size_t)(row0 + 8) * G_ + col) = v1;
        }
    }
}

__global__ void __launch_bounds__(256, 3)
f16_gemm1_kernel(const uint4* __restrict__ Ap, const uint2* __restrict__ Wp,
                 const float* __restrict__ bias, float* __restrict__ C) {
    f16_gemm_core(Ap, Wp, bias, C);
}

__global__ void __launch_bounds__(256, 3)
f16_gemm2_kernel(const uint4* A0, const uint2* P0, const float* b0, float* C0,
                 const uint4* A1, const uint2* P1, const float* b1, float* C1) {
    const uint4* A; const uint2* P; const float* bias; float* C;
    if (blockIdx.z == 0) { A = A0; P = P0; bias = b0; C = C0; }
    else                 { A = A1; P = P1; bias = b1; C = C1; }
    f16_gemm_core(A, P, bias, C);
}

// ---------------------------------------------------------------------------
// Weight prepack: fp16 hi only. uint2 e = g*32+lane:
// (bh pair k=2tg,2tg+1 ; bh pair k=2tg+8,2tg+9), col = ct*64+g*8+(lane>>2).
// ---------------------------------------------------------------------------
__global__ void prepack_kernel(const float* __restrict__ Wi,
                               const float* __restrict__ Wh,
                               uint2* __restrict__ Wp) {
    __shared__ float tile[16][64];
    const int ct = blockIdx.x, ch = blockIdx.y, z = blockIdx.z;
    const float* src = (z < 2 ? Wi : Wh) + (size_t)(z & 1) * D_ * G_;
    const int tid = threadIdx.x;

#pragma unroll
    for (int i = 0; i < 4; i++) {
        int s = tid + i * 256;
        int kk = s >> 6, n = s & 63;
        tile[kk][n] = src[(size_t)(ch * BK + kk) * G_ + ct * 64 + n];
    }
    __syncthreads();

    uint2* dst = Wp + ((size_t)z * CT_ + ct) * (NCHUNK * B_U2) + (size_t)ch * B_U2;
    if (tid < 256) {
        int lane = tid & 31, g = tid >> 5;
        int nl = g * 8 + (lane >> 2);
        int tg = lane & 3;
        uint2 q;
        q.x = pack2(f2h(tile[2 * tg][nl]),     f2h(tile[2 * tg + 1][nl]));
        q.y = pack2(f2h(tile[2 * tg + 8][nl]), f2h(tile[2 * tg + 9][nl]));
        dst[tid] = q;
    }
}

// ---------------------------------------------------------------------------
// x prepack: x row (b,t,n) -> t-major packed row t*MRP + b*N + n
// ---------------------------------------------------------------------------
__global__ void xpack_kernel(const float* __restrict__ x, uint4* __restrict__ xp) {
    int min_ = blockIdx.x;
    int n = min_ % N_;
    int t = (min_ / N_) % T_;
    int b = min_ / (N_ * T_);
    int m = t * MRP + b * N_ + n;
    int tid = threadIdx.x;
    float4 v = reinterpret_cast<const float4*>(x + (size_t)min_ * D_)[tid];
    float y[4] = { v.x, v.y, v.z, v.w };
    write_packed_fp16((uint32_t*)xp, m, tid * 4, y);
}

// ---------------------------------------------------------------------------
// Fused GRU cell + LayerNorm
// ---------------------------------------------------------------------------
__device__ __forceinline__ float sigf(float v) { return 1.f / (1.f + expf(-v)); }

__device__ __forceinline__ void cell_body(const float* __restrict__ gi,
                                          const float* __restrict__ ghrow,
                                          float* __restrict__ hrow,
                                          uint32_t* __restrict__ hpack, int m,
                                          const float* __restrict__ gamma,
                                          const float* __restrict__ beta,
                                          float* __restrict__ o2) {
    const float4* gi4 = reinterpret_cast<const float4*>(gi);
    const float4* gh4 = reinterpret_cast<const float4*>(ghrow);
    float4* h4 = reinterpret_cast<float4*>(hrow);
    int tid = threadIdx.x;

    float4 ir = gi4[tid], iz = gi4[128 + tid], inn = gi4[256 + tid];
    float4 hr = gh4[tid], hz = gh4[128 + tid], hn = gh4[256 + tid];
    float4 hv = h4[tid];

    float o[4];
    {
        float rr, z, nv;
        rr = sigf(ir.x + hr.x); z = sigf(iz.x + hz.x); nv = tanhf(inn.x + rr * hn.x);
        o[0] = nv + z * (hv.x - nv);
        rr = sigf(ir.y + hr.y); z = sigf(iz.y + hz.y); nv = tanhf(inn.y + rr * hn.y);
        o[1] = nv + z * (hv.y - nv);
        rr = sigf(ir.z + hr.z); z = sigf(iz.z + hz.z); nv = tanhf(inn.z + rr * hn.z);
        o[2] = nv + z * (hv.z - nv);
        rr = sigf(ir.w + hr.w); z = sigf(iz.w + hz.w); nv = tanhf(inn.w + rr * hn.w);
        o[3] = nv + z * (hv.w - nv);
    }
    float s = o[0] + o[1] + o[2] + o[3];
    float s2 = o[0]*o[0] + o[1]*o[1] + o[2]*o[2] + o[3]*o[3];
#pragma unroll
    for (int off = 16; off > 0; off >>= 1) {
        s  += __shfl_xor_sync(0xffffffffu, s,  off);
        s2 += __shfl_xor_sync(0xffffffffu, s2, off);
    }
    __shared__ float sh[4], sh2[4];
    int w = tid >> 5;
    if ((tid & 31) == 0) { sh[w] = s; sh2[w] = s2; }
    __syncthreads();
    s  = sh[0]  + sh[1]  + sh[2]  + sh[3];
    s2 = sh2[0] + sh2[1] + sh2[2] + sh2[3];
    float mu  = s * (1.f / D_);
    float var = s2 * (1.f / D_) - mu * mu;
    float inv = rsqrtf(var + 1e-5f);

    const float4 g4 = reinterpret_cast<const float4*>(gamma)[tid];
    const float4 b4 = reinterpret_cast<const float4*>(beta)[tid];
    float y[4];
    y[0] = (o[0] - mu) * inv * g4.x + b4.x;
    y[1] = (o[1] - mu) * inv * g4.y + b4.y;
    y[2] = (o[2] - mu) * inv * g4.z + b4.z;
    y[3] = (o[3] - mu) * inv * g4.w + b4.w;
    h4[tid] = make_float4(y[0], y[1], y[2], y[3]);
    write_packed_fp16(hpack, m, tid * 4, y);
    if (o2) reinterpret_cast<float4*>(o2)[tid] =
        make_float4(y[0], y[1], y[2], y[3]);
}

__global__ void __launch_bounds__(128)
gru_cell0(const float* __restrict__ gi0, int t,
          const float* __restrict__ gh, float* __restrict__ h,
          uint32_t* __restrict__ hpack,
          const float* __restrict__ gamma, const float* __restrict__ beta) {
    int m = blockIdx.x;
    const float* gi = gi0 + ((size_t)t * MRP + m) * G_;
    cell_body(gi, gh + (size_t)m * G_, h + (size_t)m * D_, hpack, m,
              gamma, beta, nullptr);
}

__global__ void __launch_bounds__(128)
gru_cell1(const float* __restrict__ gi1, const float* __restrict__ gh1,
          float* __restrict__ h1s, uint32_t* __restrict__ h1p,
          const float* __restrict__ gamma, const float* __restrict__ beta,
          float* __restrict__ out, int t) {
    int m = blockIdx.x;
    int b = m / N_, n = m % N_;
    float* o2 = out + ((size_t)(b * T_ + t) * N_ + n) * D_;
    cell_body(gi1 + (size_t)m * G_, gh1 + (size_t)m * G_,
              h1s + (size_t)m * D_, h1p, m, gamma + D_, beta + D_, o2);
}

// ---------------------------------------------------------------------------
__global__ void init_h_kernel(const float* __restrict__ h0,
                              float* __restrict__ h0s, float* __restrict__ h1s,
                              uint32_t* __restrict__ h0p_init,
                              uint32_t* __restrict__ h1p) {
    int row = blockIdx.x;
    int n = row % N_;
    int l = (row / N_) % 2;
    int b = row / (2 * N_);
    int tid = threadIdx.x;
    int m = b * N_ + n;
    float4 v = reinterpret_cast<const float4*>(h0 + (size_t)row * D_)[tid];
    float* hs = (l == 0) ? h0s : h1s;
    reinterpret_cast<float4*>(hs + (size_t)m * D_)[tid] = v;
    float y[4] = { v.x, v.y, v.z, v.w };
    write_packed_fp16((l == 0) ? h0p_init : h1p, m, tid * 4, y);
}

__global__ void write_hidden_kernel(const float* __restrict__ h0s,
                                    const float* __restrict__ h1s,
                                    float* __restrict__ dst) {
    int i = blockIdx.x * blockDim.x + threadIdx.x;
    if (i >= 2 * MR * D_) return;
    int d = i % D_;
    int r = i / D_;
    int n = r % N_; r /= N_;
    int l = r % 2;
    int b = r / 2;
    const float* src = (l == 0) ? h0s : h1s;
    dst[i] = src[((size_t)b * N_ + n) * D_ + d];
}

// ---------------------------------------------------------------------------
extern "C" void kernel_launch(void* const* d_in, const int* in_sizes, int n_in,
                              void* d_out, int out_size) {
    (void)in_sizes; (void)n_in;
    const float* x     = (const float*)d_in[0];
    const float* h0    = (const float*)d_in[1];
    const float* Wi    = (const float*)d_in[2];
    const float* bi    = (const float*)d_in[3];
    const float* Wh    = (const float*)d_in[4];
    const float* bh    = (const float*)d_in[5];
    const float* gamma = (const float*)d_in[6];
    const float* beta  = (const float*)d_in[7];
    float* out = (float*)d_out;

    float *gi0, *gh0, *gi1, *gh1, *h0s, *h1s;
    uint4 *h0p, *h1p, *xp;
    uint2 *Wp;
    cudaGetSymbolAddress((void**)&gi0, g_gi0);
    cudaGetSymbolAddress((void**)&gh0, g_gh0);
    cudaGetSymbolAddress((void**)&gi1, g_gi1);
    cudaGetSymbolAddress((void**)&gh1, g_gh1);
    cudaGetSymbolAddress((void**)&h0s, g_h0s);
    cudaGetSymbolAddress((void**)&h1s, g_h1s);
    cudaGetSymbolAddress((void**)&h0p, g_h0p);
    cudaGetSymbolAddress((void**)&h1p, g_h1p);
    cudaGetSymbolAddress((void**)&xp,  g_xp);
    cudaGetSymbolAddress((void**)&Wp,  g_Wp);

    cudaFuncSetAttribute(f16_gemm1_kernel,
                         cudaFuncAttributeMaxDynamicSharedMemorySize, SMEM_BYTES);
    cudaFuncSetAttribute(f16_gemm2_kernel,
                         cudaFuncAttributeMaxDynamicSharedMemorySize, SMEM_BYTES);

    static cudaStream_t s_hi = nullptr, s_L1 = nullptr, s_bg = nullptr;
    static cudaEvent_t ev_fork, ev_hi_done, ev_L1_done;
    static cudaEvent_t ev_gi0[T_], ev_h0[T_], ev_gi1[T_];
    if (!s_hi) {
        int lo = 0, hi = 0;
        cudaDeviceGetStreamPriorityRange(&lo, &hi);
        cudaStreamCreateWithPriority(&s_hi, cudaStreamNonBlocking, hi);
        cudaStreamCreateWithPriority(&s_L1, cudaStreamNonBlocking, lo);
        cudaStreamCreateWithPriority(&s_bg, cudaStreamNonBlocking, lo);
        cudaEventCreateWithFlags(&ev_fork,    cudaEventDisableTiming);
        cudaEventCreateWithFlags(&ev_hi_done, cudaEventDisableTiming);
        cudaEventCreateWithFlags(&ev_L1_done, cudaEventDisableTiming);
        for (int i = 0; i < T_; i++) {
            cudaEventCreateWithFlags(&ev_gi0[i], cudaEventDisableTiming);
            cudaEventCreateWithFlags(&ev_h0[i],  cudaEventDisableTiming);
            cudaEventCreateWithFlags(&ev_gi1[i], cudaEventDisableTiming);
        }
    }

    const uint2* Wi0p = Wp;
    const uint2* Wi1p = Wp + WU2_PER_W;
    const uint2* Wh0p = Wp + 2 * WU2_PER_W;
    const uint2* Wh1p = Wp + 3 * WU2_PER_W;
    uint4* h0pb[2] = { h0p, h0p + HQ };

    // ---- prologue on stream 0 ----
    prepack_kernel<<<dim3(CT_, NCHUNK, 4), 256>>>(Wi, Wh, Wp);
    init_h_kernel<<<2 * MR, 128>>>(h0, h0s, h1s,
                                   (uint32_t*)h0pb[1], (uint32_t*)h1p);
    xpack_kernel<<<MB_, 128>>>(x, xp);

    cudaEventRecord(ev_fork, 0);
    cudaStreamWaitEvent(s_bg, ev_fork, 0);
    cudaStreamWaitEvent(s_hi, ev_fork, 0);

    // background: gi0 slices 1..T-1
    for (int t = 1; t < T_; t++) {
        f16_gemm1_kernel<<<dim3(CT_, RT_R), 256, SMEM_BYTES, s_bg>>>(
            xp + (size_t)t * HQ, Wi0p, bi, gi0 + (size_t)t * MRP * G_);
        cudaEventRecord(ev_gi0[t], s_bg);
    }

    // critical chain start: gi0 slice 0, GH0(0), cell0(0)
    f16_gemm1_kernel<<<dim3(CT_, RT_R), 256, SMEM_BYTES, s_hi>>>(
        xp, Wi0p, bi, gi0);
    f16_gemm1_kernel<<<dim3(CT_, RT_R), 256, SMEM_BYTES, s_hi>>>(
        h0pb[1], Wh0p, bh, gh0);
    gru_cell0<<<MR, 128, 0, s_hi>>>(gi0, 0, gh0, h0s,
                                    (uint32_t*)h0pb[0], gamma, beta);
    cudaEventRecord(ev_h0[0], s_hi);

    for (int t = 0; t < T_; t++) {
        // --- layer-1 work for step t (lags on s_L1) ---
        cudaStreamWaitEvent(s_L1, ev_h0[t], 0);
        f16_gemm2_kernel<<<dim3(CT_, RT_R, 2), 256, SMEM_BYTES, s_L1>>>(
            h0pb[t & 1], Wi1p, bi + G_, gi1,
            h1p,         Wh1p, bh + G_, gh1);
        cudaEventRecord(ev_gi1[t], s_L1);
        gru_cell1<<<MR, 128, 0, s_L1>>>(gi1, gh1, h1s, (uint32_t*)h1p,
                                        gamma, beta, out, t);

        // --- layer-0 critical chain: produce cell0(t+1) ---
        if (t < T_ - 1) {
            f16_gemm1_kernel<<<dim3(CT_, RT_R), 256, SMEM_BYTES, s_hi>>>(
                h0pb[t & 1], Wh0p, bh, gh0);
            cudaStreamWaitEvent(s_hi, ev_gi0[t + 1], 0);
            if (t >= 1)
                cudaStreamWaitEvent(s_hi, ev_gi1[t - 1], 0);  // h0p reuse safety
            gru_cell0<<<MR, 128, 0, s_hi>>>(gi0, t + 1, gh0, h0s,
                                            (uint32_t*)h0pb[(t + 1) & 1],
                                            gamma, beta);
            cudaEventRecord(ev_h0[t + 1], s_hi);
        }
    }

    cudaEventRecord(ev_hi_done, s_hi);
    cudaEventRecord(ev_L1_done, s_L1);
    cudaStreamWaitEvent(0, ev_hi_done, 0);
    cudaStreamWaitEvent(0, ev_L1_done, 0);

    long long need = (long long)MB_ * D_ + (long long)2 * MR * D_;
    if ((long long)out_size >= need) {
        int tot = 2 * MR * D_;
        write_hidden_kernel<<<(tot + 255) / 256, 256>>>(h0s, h1s,
                                                        out + (size_t)MB_ * D_);
    }
}